// round 11
// baseline (speedup 1.0000x reference)
#include <cuda_runtime.h>
#include <cuda_bf16.h>
#include <cstdint>
#include <math.h>

// Problem constants
#define Bq   16
#define Tq   1024
#define Dq   512
#define Vq   5000
#define Lq   128
#define VP   5120            // V padded to multiple of 128
#define NT   40              // VP / 128 column tiles
#define BT   (Bq*Tq)         // 16384 rows
#define NEGF (-1e30f)

// ---------------- scratch (static device globals; no allocation) ----------------
__device__ __align__(16) __nv_bfloat16 g_hsb[BT*Dq];      // hs in bf16
__device__ __align__(16) __nv_bfloat16 g_wt[VP*Dq];       // W transposed: [v][d], bf16, pad rows zero
__device__ float g_gbuf[BT*130];                          // logits at first-occurrence symbols
__device__ float g_lp[BT*130];                            // LOG-probs at symbol j (0=blank,1..128=labels)
__device__ float g_partial[BT*NT];                        // per-(row, ntile) exp-sums
__device__ int   g_inv[Bq*Vq];                            // vocab -> first symbol index j (or -1)
__device__ int   g_rep[Bq*129];                           // j -> first occurrence j'
__device__ float g_loss[Bq];

// ---------------- helpers ----------------
__device__ __forceinline__ void cp16s(uint32_t smem_addr, const void* gmem) {
    asm volatile("cp.async.cg.shared.global [%0], [%1], 16;\n" :: "r"(smem_addr), "l"(gmem));
}
__device__ __forceinline__ void ldsm4(uint32_t& r0, uint32_t& r1, uint32_t& r2, uint32_t& r3,
                                      uint32_t addr) {
    asm volatile("ldmatrix.sync.aligned.m8n8.x4.shared.b16 {%0,%1,%2,%3}, [%4];\n"
                 : "=r"(r0), "=r"(r1), "=r"(r2), "=r"(r3) : "r"(addr));
}
__device__ __forceinline__ void mma_bf16(
    float& d0, float& d1, float& d2, float& d3,
    unsigned a0, unsigned a1, unsigned a2, unsigned a3,
    unsigned b0, unsigned b1)
{
    asm volatile(
        "mma.sync.aligned.m16n8k16.row.col.f32.bf16.bf16.f32 "
        "{%0,%1,%2,%3}, {%4,%5,%6,%7}, {%8,%9}, {%0,%1,%2,%3};\n"
        : "+f"(d0), "+f"(d1), "+f"(d2), "+f"(d3)
        : "r"(a0), "r"(a1), "r"(a2), "r"(a3), "r"(b0), "r"(b1));
}

// ---------------- conversion kernels ----------------
__global__ void k_cvt_hs(const float4* __restrict__ hs4) {
    int i = blockIdx.x * 256 + threadIdx.x;
    if (i < BT*Dq/4) {
        float4 v = hs4[i];
        __nv_bfloat162* o = (__nv_bfloat162*)g_hsb;
        o[2*i]   = __floats2bfloat162_rn(v.x, v.y);
        o[2*i+1] = __floats2bfloat162_rn(v.z, v.w);
    }
}

// Tiled transpose: W[D][V] f32 -> g_wt[VP][D] bf16 (pad rows v>=Vq zeroed)
__global__ void k_cvt_wt(const float* __restrict__ W) {
    __shared__ float tile[32][33];
    int v0 = blockIdx.x * 32, d0 = blockIdx.y * 32;
    int tx = threadIdx.x, ty = threadIdx.y;          // 32 x 8
    #pragma unroll
    for (int i = 0; i < 32; i += 8) {
        int d = d0 + ty + i, v = v0 + tx;
        tile[ty + i][tx] = (v < Vq) ? W[(size_t)d*Vq + v] : 0.0f;
    }
    __syncthreads();
    #pragma unroll
    for (int i = 0; i < 32; i += 8) {
        int v = v0 + ty + i, d = d0 + tx;
        g_wt[(size_t)v*Dq + d] = __float2bfloat16(tile[tx][ty + i]);
    }
}

// ---------------- per-batch symbol maps (parallel first-occurrence) ----------------
__global__ void k_prep(const int* __restrict__ ys_pad) {
    int b = blockIdx.x, tid = threadIdx.x;
    __shared__ int sym[129];
    if (tid == 0) sym[0] = 0;                              // blank
    if (tid >= 1 && tid <= 128) sym[tid] = ys_pad[b*Lq + tid - 1];
    for (int i = tid; i < Vq; i += 256) g_inv[b*Vq + i] = 0x7fffffff;
    __syncthreads();
    if (tid <= 128) atomicMin(&g_inv[b*Vq + sym[tid]], tid);
    __syncthreads();
    if (tid <= 128) g_rep[b*129 + tid] = g_inv[b*Vq + sym[tid]];
    __syncthreads();
    for (int i = tid; i < Vq; i += 256)
        if (g_inv[b*Vq + i] == 0x7fffffff) g_inv[b*Vq + i] = -1;
}

// ---------------- fused bf16 GEMM: 4-stage cp.async + ldmatrix + mma.sync ----------------
// smem layout (dynamic, bytes):
//   A stages: 4 x 128 x 40 bf16 = 4 x 10240             [0,      40960)
//   B stages: 4 x 128 x 40 bf16 = 4 x 10240             [40960,  81920)
//   bias 128 f32 / invs 128 int / rsum 128x2 f32
#define SMA_OFF   0
#define SMB_OFF   40960
#define SMBIAS    81920
#define SMINVS    82432
#define SMRSUM    82944
#define SM_TOTAL  83968
#define STAGE_B   10240

__global__ __launch_bounds__(256, 2) void k_gemm(const float* __restrict__ bias) {
    extern __shared__ __align__(16) char smem[];
    const int tid  = threadIdx.x;
    const int lane = tid & 31, wid = tid >> 5;
    const int g  = lane >> 2, tg = lane & 3;
    const int wm = wid & 3,  wn = wid >> 2;         // 4x2 warp grid, warp tile 32x64
    const int n0 = blockIdx.x * 128;
    const int rowg0 = blockIdx.y * 128;
    const int b = rowg0 >> 10;

    __nv_bfloat16* As = (__nv_bfloat16*)(smem + SMA_OFF);  // [stage][128][40]
    __nv_bfloat16* Bs = (__nv_bfloat16*)(smem + SMB_OFF);
    float* biass = (float*)(smem + SMBIAS);
    int*   invs  = (int*)  (smem + SMINVS);
    float* rsum  = (float*)(smem + SMRSUM);

    if (tid < 128) {
        int v = n0 + tid;
        invs[tid]  = (v < Vq) ? g_inv[b*Vq + v] : -1;
        biass[tid] = (v < Vq) ? bias[v] : 0.0f;
    }

    // ldmatrix per-lane byte offsets (within one stage)
    const int lr = lane & 15, lc = (lane >> 4) << 3;
    const uint32_t aBase = (uint32_t)__cvta_generic_to_shared(As);
    const uint32_t bBase = (uint32_t)__cvta_generic_to_shared(Bs);
    const uint32_t aoff0 = ((wm*32      + lr)*40 + lc)*2;
    const uint32_t aoff1 = ((wm*32 + 16 + lr)*40 + lc)*2;
    uint32_t boff[4];
    #pragma unroll
    for (int nt = 0; nt < 4; nt++) boff[nt] = ((wn*64 + nt*16 + lr)*40 + lc)*2;

    float acc[2][8][4];
    #pragma unroll
    for (int im = 0; im < 2; im++)
        #pragma unroll
        for (int in_ = 0; in_ < 8; in_++)
            #pragma unroll
            for (int c = 0; c < 4; c++) acc[im][in_][c] = 0.0f;

    // loader: hoisted base pointers, increment-only addressing (cuts ALU IMADs)
    const int lrow = tid >> 2, lkp = (tid & 3) << 3;
    const __nv_bfloat16* pA0 = g_hsb + (size_t)(rowg0 + lrow)*Dq + lkp;
    const __nv_bfloat16* pA1 = pA0 + (size_t)64*Dq;
    const __nv_bfloat16* pB0 = g_wt  + (size_t)(n0   + lrow)*Dq + lkp;
    const __nv_bfloat16* pB1 = pB0 + (size_t)64*Dq;
    const uint32_t dOff = (uint32_t)(lrow*40 + lkp)*2;     // byte offset within a stage
    const uint32_t dA = aBase + dOff, dB = bBase + dOff;

    auto loadStage = [&](int kt) {
        if (kt < 16) {
            const int st = kt & 3;
            const int ko = kt * 32;                         // element offset in k
            const uint32_t sOff = (uint32_t)st * STAGE_B;
            cp16s(dA + sOff,        pA0 + ko);
            cp16s(dA + sOff + 5120, pA1 + ko);
            cp16s(dB + sOff,        pB0 + ko);
            cp16s(dB + sOff + 5120, pB1 + ko);
        }
        asm volatile("cp.async.commit_group;\n");
    };

    loadStage(0);
    loadStage(1);
    loadStage(2);

    #pragma unroll 1
    for (int kt = 0; kt < 16; kt++) {
        asm volatile("cp.async.wait_group 2;\n");
        __syncthreads();                      // stage kt ready; stage (kt-1)&3 free
        loadStage(kt + 3);                    // overlap next loads with this stage's MMAs

        const uint32_t ab = aBase + (kt & 3)*STAGE_B;
        const uint32_t bb = bBase + (kt & 3)*STAGE_B;
        #pragma unroll
        for (int ks = 0; ks < 2; ks++) {
            uint32_t ko = ks * 32;
            uint32_t a0[4], a1[4], bm[4][4];
            ldsm4(a0[0], a0[1], a0[2], a0[3], ab + aoff0 + ko);
            ldsm4(a1[0], a1[1], a1[2], a1[3], ab + aoff1 + ko);
            #pragma unroll
            for (int nt = 0; nt < 4; nt++)
                ldsm4(bm[nt][0], bm[nt][1], bm[nt][2], bm[nt][3], bb + boff[nt] + ko);
            #pragma unroll
            for (int nt = 0; nt < 4; nt++) {
                #pragma unroll
                for (int h = 0; h < 2; h++) {
                    int in_ = nt*2 + h;
                    unsigned b0 = bm[nt][h], b1 = bm[nt][2 + h];
                    mma_bf16(acc[0][in_][0], acc[0][in_][1], acc[0][in_][2], acc[0][in_][3],
                             a0[0], a0[1], a0[2], a0[3], b0, b1);
                    mma_bf16(acc[1][in_][0], acc[1][in_][1], acc[1][in_][2], acc[1][in_][3],
                             a1[0], a1[1], a1[2], a1[3], b0, b1);
                }
            }
        }
    }
    __syncthreads();   // all MMAs done before rsum reuse below

    // Epilogue: bias add, exp-sum per row, sparse symbol scatter
    #pragma unroll
    for (int im = 0; im < 2; im++) {
        #pragma unroll
        for (int rh = 0; rh < 2; rh++) {
            int m = wm*32 + im*16 + g + rh*8;
            float* gb = g_gbuf + (size_t)(rowg0 + m)*130;
            float s = 0.0f;
            #pragma unroll
            for (int in_ = 0; in_ < 8; in_++) {
                #pragma unroll
                for (int cc = 0; cc < 2; cc++) {
                    int n = wn*64 + in_*8 + tg*2 + cc;
                    float x = acc[im][in_][rh*2 + cc] + biass[n];
                    if (n0 + n < Vq) {
                        s += __expf(x);
                        int j = invs[n];
                        if (j >= 0) gb[j] = x;
                    }
                }
            }
            s += __shfl_xor_sync(0xffffffffu, s, 1);
            s += __shfl_xor_sync(0xffffffffu, s, 2);
            if (tg == 0) rsum[m*2 + wn] = s;
        }
    }
    __syncthreads();
    if (tid < 128)
        g_partial[(size_t)(rowg0 + tid)*NT + blockIdx.x] = rsum[tid*2] + rsum[tid*2 + 1];
}

// ---------------- fused: reduce exp-sums -> lse, replicate dups, subtract ----------------
__global__ __launch_bounds__(192) void k_lsedup() {
    int r = blockIdx.x;
    int t = threadIdx.x;
    __shared__ float ws[6];
    __shared__ float lse_s;
    float s = (t < NT) ? g_partial[(size_t)r*NT + t] : 0.0f;
    #pragma unroll
    for (int o = 16; o > 0; o >>= 1) s += __shfl_xor_sync(0xffffffffu, s, o);
    if ((t & 31) == 0) ws[t >> 5] = s;
    __syncthreads();
    if (t == 0) lse_s = __logf(ws[0] + ws[1] + ws[2] + ws[3] + ws[4] + ws[5]);
    __syncthreads();
    if (t < 129) {
        int bb = r >> 10;
        g_lp[(size_t)r*130 + t] = g_gbuf[(size_t)r*130 + g_rep[bb*129 + t]] - lse_s;
    }
}

// ---------------- CTC forward: log-domain (known correct), depth-4 prefetch ----------------
__global__ __launch_bounds__(288) void k_ctc(const int* __restrict__ ys_pad,
                                             const int* __restrict__ hlens,
                                             const int* __restrict__ ys_lens) {
    const int b = blockIdx.x, s = threadIdx.x;   // 288 threads, states 0..256 active
    __shared__ float bufA[259], bufB[259];       // alpha at offset +2 (pads [0..1] = NEG)
    __shared__ int ysS[128];

    const int hl = hlens[b];
    const int yl = ys_lens[b];
    const float* lpb = g_lp + (size_t)b * Tq * 130;

    if (s < 128) ysS[s] = ys_pad[b*Lq + s];
    if (s < 259) { bufA[s] = NEGF; bufB[s] = NEGF; }
    __syncthreads();

    const bool active = (s < 257);
    int jj = 0;
    bool allow = false;
    if (active && (s & 1)) {
        int k = s >> 1;                           // s = 2k+1 -> label k, lp index k+1
        jj = k + 1;
        allow = (k == 0) || (ysS[k] != ysS[k - 1]);
    }

    if (s == 0) bufA[2] = lpb[0];                 // alpha0[0] = lp_ext[0,0] (blank)
    if (s == 1) bufA[3] = lpb[1];                 // alpha0[1] = lp_ext[0,1]
    __syncthreads();

    float* cur = bufA;
    float* nxt = bufB;

    // depth-4 register prefetch of this state's lp stream (covers far-L2 latency)
    float p0 = 0.0f, p1 = 0.0f, p2 = 0.0f, p3 = 0.0f;
    if (active) {
        p0 = __ldg(&lpb[1*130 + jj]);
        p1 = __ldg(&lpb[2*130 + jj]);
        p2 = __ldg(&lpb[3*130 + jj]);
        p3 = __ldg(&lpb[4*130 + jj]);
    }

    for (int t = 1; t < hl; t++) {
        float lpv = p0;
        p0 = p1; p1 = p2; p2 = p3;
        int tn = t + 4; if (tn > Tq - 1) tn = Tq - 1;
        if (active) p3 = __ldg(&lpb[(size_t)tn * 130 + jj]);

        if (active) {
            float a1 = cur[2 + s];
            float a2 = cur[1 + s];
            float a3 = allow ? cur[s] : NEGF;
            float m = fmaxf(fmaxf(a1, a2), a3);
            m = fmaxf(m, NEGF);
            float r = __expf(a1 - m) + __expf(a2 - m) + __expf(a3 - m);
            nxt[2 + s] = m + __logf(r) + lpv;
        }
        __syncthreads();
        float* tmp = cur; cur = nxt; nxt = tmp;
    }

    if (s == 0) {
        int i1 = 2 * yl;
        int i2 = i1 - 1; if (i2 < 0) i2 = 0;
        float a = cur[2 + i1], c = cur[2 + i2];
        float m = fmaxf(a, c);
        float ll = m + __logf(__expf(a - m) + __expf(c - m));
        float L = -ll;
        if (!isfinite(L) || L >= 1e29f) L = 0.0f;  // zero_infinity
        g_loss[b] = L;
    }
}

// ---------------- finalize: sum(loss) / sum(ys_lens) ----------------
__global__ void k_finalize(const int* __restrict__ ys_lens, float* __restrict__ out) {
    int t = threadIdx.x;
    float s  = (t < Bq) ? g_loss[t] : 0.0f;
    float yn = (t < Bq) ? (float)ys_lens[t] : 0.0f;
    #pragma unroll
    for (int o = 16; o > 0; o >>= 1) {
        s  += __shfl_xor_sync(0xffffffffu, s,  o);
        yn += __shfl_xor_sync(0xffffffffu, yn, o);
    }
    if (t == 0) out[0] = s / yn;
}

// ---------------- launch ----------------
extern "C" void kernel_launch(void* const* d_in, const int* in_sizes, int n_in,
                              void* d_out, int out_size) {
    (void)in_sizes; (void)n_in; (void)out_size;
    const float* hs      = (const float*)d_in[0];
    const int*   hlens   = (const int*)  d_in[1];
    const int*   ys_pad  = (const int*)  d_in[2];
    const int*   ys_lens = (const int*)  d_in[3];
    const float* W       = (const float*)d_in[4];
    const float* bias    = (const float*)d_in[5];
    float*       out     = (float*)d_out;

    cudaFuncSetAttribute(k_gemm, cudaFuncAttributeMaxDynamicSharedMemorySize, SM_TOTAL);

    k_cvt_hs<<<(BT*Dq/4 + 255)/256, 256>>>((const float4*)hs);
    k_cvt_wt<<<dim3(VP/32, Dq/32), dim3(32, 8)>>>(W);
    k_prep  <<<Bq, 256>>>(ys_pad);
    k_gemm  <<<dim3(NT, BT/128), 256, SM_TOTAL>>>(bias);
    k_lsedup<<<BT, 192>>>();
    k_ctc   <<<Bq, 288>>>(ys_pad, hlens, ys_lens);
    k_finalize<<<1, 32>>>(ys_lens, out);
}

// round 12
// speedup vs baseline: 1.4235x; 1.4235x over previous
#include <cuda_runtime.h>
#include <cuda_bf16.h>
#include <cstdint>
#include <math.h>

// Problem constants
#define Bq   16
#define Tq   1024
#define Dq   512
#define Vq   5000
#define Lq   128
#define VP   5120            // V padded to multiple of 128
#define NT   40              // VP / 128 column tiles
#define BT   (Bq*Tq)         // 16384 rows
#define LPS  132             // g_lp row stride (padded: 132*4 = 528 = 33*16 bytes)
#define NEGF (-1e30f)

// ---------------- scratch (static device globals; no allocation) ----------------
__device__ __align__(16) __nv_bfloat16 g_hsb[BT*Dq];      // hs in bf16
__device__ __align__(16) __nv_bfloat16 g_wt[VP*Dq];       // W transposed: [v][d], bf16, pad rows zero
__device__ float g_gbuf[BT*130];                          // logits at first-occurrence symbols
__device__ __align__(16) float g_lp[BT*LPS];              // LOG-probs at symbol j (0=blank,1..128=labels)
__device__ float g_partial[BT*NT];                        // per-(row, ntile) exp-sums
__device__ int   g_inv[Bq*Vq];                            // vocab -> first symbol index j (or -1)
__device__ int   g_rep[Bq*129];                           // j -> first occurrence j'
__device__ float g_loss[Bq];

// ---------------- helpers ----------------
__device__ __forceinline__ void cp16s(uint32_t smem_addr, const void* gmem) {
    asm volatile("cp.async.cg.shared.global [%0], [%1], 16;\n" :: "r"(smem_addr), "l"(gmem));
}
__device__ __forceinline__ void ldsm4(uint32_t& r0, uint32_t& r1, uint32_t& r2, uint32_t& r3,
                                      uint32_t addr) {
    asm volatile("ldmatrix.sync.aligned.m8n8.x4.shared.b16 {%0,%1,%2,%3}, [%4];\n"
                 : "=r"(r0), "=r"(r1), "=r"(r2), "=r"(r3) : "r"(addr));
}
__device__ __forceinline__ void mma_bf16(
    float& d0, float& d1, float& d2, float& d3,
    unsigned a0, unsigned a1, unsigned a2, unsigned a3,
    unsigned b0, unsigned b1)
{
    asm volatile(
        "mma.sync.aligned.m16n8k16.row.col.f32.bf16.bf16.f32 "
        "{%0,%1,%2,%3}, {%4,%5,%6,%7}, {%8,%9}, {%0,%1,%2,%3};\n"
        : "+f"(d0), "+f"(d1), "+f"(d2), "+f"(d3)
        : "r"(a0), "r"(a1), "r"(a2), "r"(a3), "r"(b0), "r"(b1));
}

// ---------------- conversion kernels ----------------
__global__ void k_cvt_hs(const float4* __restrict__ hs4) {
    int i = blockIdx.x * 256 + threadIdx.x;
    if (i < BT*Dq/4) {
        float4 v = hs4[i];
        __nv_bfloat162* o = (__nv_bfloat162*)g_hsb;
        o[2*i]   = __floats2bfloat162_rn(v.x, v.y);
        o[2*i+1] = __floats2bfloat162_rn(v.z, v.w);
    }
}

// Tiled transpose: W[D][V] f32 -> g_wt[VP][D] bf16 (pad rows v>=Vq zeroed)
__global__ void k_cvt_wt(const float* __restrict__ W) {
    __shared__ float tile[32][33];
    int v0 = blockIdx.x * 32, d0 = blockIdx.y * 32;
    int tx = threadIdx.x, ty = threadIdx.y;          // 32 x 8
    #pragma unroll
    for (int i = 0; i < 32; i += 8) {
        int d = d0 + ty + i, v = v0 + tx;
        tile[ty + i][tx] = (v < Vq) ? W[(size_t)d*Vq + v] : 0.0f;
    }
    __syncthreads();
    #pragma unroll
    for (int i = 0; i < 32; i += 8) {
        int v = v0 + ty + i, d = d0 + tx;
        g_wt[(size_t)v*Dq + d] = __float2bfloat16(tile[tx][ty + i]);
    }
}

// ---------------- per-batch symbol maps (parallel first-occurrence) ----------------
__global__ void k_prep(const int* __restrict__ ys_pad) {
    int b = blockIdx.x, tid = threadIdx.x;
    __shared__ int sym[129];
    if (tid == 0) sym[0] = 0;                              // blank
    if (tid >= 1 && tid <= 128) sym[tid] = ys_pad[b*Lq + tid - 1];
    for (int i = tid; i < Vq; i += 256) g_inv[b*Vq + i] = 0x7fffffff;
    __syncthreads();
    if (tid <= 128) atomicMin(&g_inv[b*Vq + sym[tid]], tid);
    __syncthreads();
    if (tid <= 128) g_rep[b*129 + tid] = g_inv[b*Vq + sym[tid]];
    __syncthreads();
    for (int i = tid; i < Vq; i += 256)
        if (g_inv[b*Vq + i] == 0x7fffffff) g_inv[b*Vq + i] = -1;
}

// ---------------- fused bf16 GEMM: 4-stage cp.async + ldmatrix + mma.sync ----------------
// (byte-identical to the passing Round-11 version)
#define SMA_OFF   0
#define SMB_OFF   40960
#define SMBIAS    81920
#define SMINVS    82432
#define SMRSUM    82944
#define SM_TOTAL  83968
#define STAGE_B   10240

__global__ __launch_bounds__(256, 2) void k_gemm(const float* __restrict__ bias) {
    extern __shared__ __align__(16) char smem[];
    const int tid  = threadIdx.x;
    const int lane = tid & 31, wid = tid >> 5;
    const int g  = lane >> 2, tg = lane & 3;
    const int wm = wid & 3,  wn = wid >> 2;         // 4x2 warp grid, warp tile 32x64
    const int n0 = blockIdx.x * 128;
    const int rowg0 = blockIdx.y * 128;
    const int b = rowg0 >> 10;

    __nv_bfloat16* As = (__nv_bfloat16*)(smem + SMA_OFF);  // [stage][128][40]
    __nv_bfloat16* Bs = (__nv_bfloat16*)(smem + SMB_OFF);
    float* biass = (float*)(smem + SMBIAS);
    int*   invs  = (int*)  (smem + SMINVS);
    float* rsum  = (float*)(smem + SMRSUM);

    if (tid < 128) {
        int v = n0 + tid;
        invs[tid]  = (v < Vq) ? g_inv[b*Vq + v] : -1;
        biass[tid] = (v < Vq) ? bias[v] : 0.0f;
    }

    const int lr = lane & 15, lc = (lane >> 4) << 3;
    const uint32_t aBase = (uint32_t)__cvta_generic_to_shared(As);
    const uint32_t bBase = (uint32_t)__cvta_generic_to_shared(Bs);
    const uint32_t aoff0 = ((wm*32      + lr)*40 + lc)*2;
    const uint32_t aoff1 = ((wm*32 + 16 + lr)*40 + lc)*2;
    uint32_t boff[4];
    #pragma unroll
    for (int nt = 0; nt < 4; nt++) boff[nt] = ((wn*64 + nt*16 + lr)*40 + lc)*2;

    float acc[2][8][4];
    #pragma unroll
    for (int im = 0; im < 2; im++)
        #pragma unroll
        for (int in_ = 0; in_ < 8; in_++)
            #pragma unroll
            for (int c = 0; c < 4; c++) acc[im][in_][c] = 0.0f;

    const int lrow = tid >> 2, lkp = (tid & 3) << 3;
    const __nv_bfloat16* pA0 = g_hsb + (size_t)(rowg0 + lrow)*Dq + lkp;
    const __nv_bfloat16* pA1 = pA0 + (size_t)64*Dq;
    const __nv_bfloat16* pB0 = g_wt  + (size_t)(n0   + lrow)*Dq + lkp;
    const __nv_bfloat16* pB1 = pB0 + (size_t)64*Dq;
    const uint32_t dOff = (uint32_t)(lrow*40 + lkp)*2;
    const uint32_t dA = aBase + dOff, dB = bBase + dOff;

    auto loadStage = [&](int kt) {
        if (kt < 16) {
            const int st = kt & 3;
            const int ko = kt * 32;
            const uint32_t sOff = (uint32_t)st * STAGE_B;
            cp16s(dA + sOff,        pA0 + ko);
            cp16s(dA + sOff + 5120, pA1 + ko);
            cp16s(dB + sOff,        pB0 + ko);
            cp16s(dB + sOff + 5120, pB1 + ko);
        }
        asm volatile("cp.async.commit_group;\n");
    };

    loadStage(0);
    loadStage(1);
    loadStage(2);

    #pragma unroll 1
    for (int kt = 0; kt < 16; kt++) {
        asm volatile("cp.async.wait_group 2;\n");
        __syncthreads();
        loadStage(kt + 3);

        const uint32_t ab = aBase + (kt & 3)*STAGE_B;
        const uint32_t bb = bBase + (kt & 3)*STAGE_B;
        #pragma unroll
        for (int ks = 0; ks < 2; ks++) {
            uint32_t ko = ks * 32;
            uint32_t a0[4], a1[4], bm[4][4];
            ldsm4(a0[0], a0[1], a0[2], a0[3], ab + aoff0 + ko);
            ldsm4(a1[0], a1[1], a1[2], a1[3], ab + aoff1 + ko);
            #pragma unroll
            for (int nt = 0; nt < 4; nt++)
                ldsm4(bm[nt][0], bm[nt][1], bm[nt][2], bm[nt][3], bb + boff[nt] + ko);
            #pragma unroll
            for (int nt = 0; nt < 4; nt++) {
                #pragma unroll
                for (int h = 0; h < 2; h++) {
                    int in_ = nt*2 + h;
                    unsigned b0 = bm[nt][h], b1 = bm[nt][2 + h];
                    mma_bf16(acc[0][in_][0], acc[0][in_][1], acc[0][in_][2], acc[0][in_][3],
                             a0[0], a0[1], a0[2], a0[3], b0, b1);
                    mma_bf16(acc[1][in_][0], acc[1][in_][1], acc[1][in_][2], acc[1][in_][3],
                             a1[0], a1[1], a1[2], a1[3], b0, b1);
                }
            }
        }
    }
    __syncthreads();

    #pragma unroll
    for (int im = 0; im < 2; im++) {
        #pragma unroll
        for (int rh = 0; rh < 2; rh++) {
            int m = wm*32 + im*16 + g + rh*8;
            float* gb = g_gbuf + (size_t)(rowg0 + m)*130;
            float s = 0.0f;
            #pragma unroll
            for (int in_ = 0; in_ < 8; in_++) {
                #pragma unroll
                for (int cc = 0; cc < 2; cc++) {
                    int n = wn*64 + in_*8 + tg*2 + cc;
                    float x = acc[im][in_][rh*2 + cc] + biass[n];
                    if (n0 + n < Vq) {
                        s += __expf(x);
                        int j = invs[n];
                        if (j >= 0) gb[j] = x;
                    }
                }
            }
            s += __shfl_xor_sync(0xffffffffu, s, 1);
            s += __shfl_xor_sync(0xffffffffu, s, 2);
            if (tg == 0) rsum[m*2 + wn] = s;
        }
    }
    __syncthreads();
    if (tid < 128)
        g_partial[(size_t)(rowg0 + tid)*NT + blockIdx.x] = rsum[tid*2] + rsum[tid*2 + 1];
}

// ---------------- fused: reduce exp-sums -> lse, replicate dups, subtract ----------------
__global__ __launch_bounds__(192) void k_lsedup() {
    int r = blockIdx.x;
    int t = threadIdx.x;
    __shared__ float ws[6];
    __shared__ float lse_s;
    float s = (t < NT) ? g_partial[(size_t)r*NT + t] : 0.0f;
    #pragma unroll
    for (int o = 16; o > 0; o >>= 1) s += __shfl_xor_sync(0xffffffffu, s, o);
    if ((t & 31) == 0) ws[t >> 5] = s;
    __syncthreads();
    if (t == 0) lse_s = __logf(ws[0] + ws[1] + ws[2] + ws[3] + ws[4] + ws[5]);
    __syncthreads();
    if (t < 129) {
        int bb = r >> 10;
        g_lp[(size_t)r*LPS + t] = g_gbuf[(size_t)r*130 + g_rep[bb*129 + t]] - lse_s;
    }
}

// ---------------- CTC forward: log-domain, smem-staged lp chunks (no per-step LDG) ----------------
// lp rows for 64 timesteps (64 x 132 floats = 33792 B, contiguous) are staged into
// a double-buffered dynamic-smem region with cp.async; the step loop is pure smem.
#define CHK   64
#define CHKB  (CHK*LPS*4)     // 33792 bytes per chunk buffer
__global__ __launch_bounds__(288) void k_ctc(const int* __restrict__ ys_pad,
                                             const int* __restrict__ hlens,
                                             const int* __restrict__ ys_lens) {
    extern __shared__ __align__(16) float slp[];   // 2 x CHK x LPS floats
    __shared__ float bufA[259], bufB[259];         // alpha at offset +2 (pads [0..1] = NEG)
    __shared__ int ysS[128];

    const int b = blockIdx.x, s = threadIdx.x;     // 288 threads, states 0..256 active
    const int hl = hlens[b];
    const int yl = ys_lens[b];
    const float* lpb = g_lp + (size_t)b * Tq * LPS;
    const uint32_t slpBase = (uint32_t)__cvta_generic_to_shared(slp);

    if (s < 128) ysS[s] = ys_pad[b*Lq + s];
    if (s < 259) { bufA[s] = NEGF; bufB[s] = NEGF; }

    // stage chunk c (rows [c*64, c*64+64) of lpb) into buffer c&1
    auto stage = [&](int c) {
        const float* src = lpb + ((size_t)c << 6) * LPS;
        uint32_t dst = slpBase + (uint32_t)(c & 1) * CHKB;
        #pragma unroll
        for (int it = 0; it < 8; it++) {
            int i = s + it*288;                    // 2112 x 16B units
            if (i < CHK*33) cp16s(dst + i*16, src + i*4);
        }
        asm volatile("cp.async.commit_group;\n");
    };
    stage(0);

    __syncthreads();
    const bool active = (s < 257);
    int jj = 0;
    bool allow = false;
    if (active && (s & 1)) {
        int k = s >> 1;                            // s = 2k+1 -> label k, lp index k+1
        jj = k + 1;
        allow = (k == 0) || (ysS[k] != ysS[k - 1]);
    }

    if (s == 0) bufA[2] = lpb[0];                  // alpha0[0] = lp_ext[0,0] (blank)
    if (s == 1) bufA[3] = lpb[1];                  // alpha0[1] = lp_ext[0,1]

    float* cur = bufA;
    float* nxt = bufB;

    const int nch = (hl + CHK - 1) >> 6;           // chunks covering t in [0, hl)
    #pragma unroll 1
    for (int c = 0; c < nch; c++) {
        asm volatile("cp.async.wait_group 0;\n");  // chunk c staged
        __syncthreads();
        if (c + 1 < nch) stage(c + 1);             // overlap next chunk load with compute

        const float* lps = slp + (c & 1) * (CHK*LPS);
        const int t0 = (c == 0) ? 1 : (c << 6);
        const int t1 = min(hl, (c + 1) << 6);
        const int tb = c << 6;
        #pragma unroll 1
        for (int t = t0; t < t1; t++) {
            if (active) {
                float lpv = lps[(t - tb)*LPS + jj];
                float a1 = cur[2 + s];
                float a2 = cur[1 + s];
                float a3 = allow ? cur[s] : NEGF;
                float m = fmaxf(fmaxf(a1, a2), a3);
                m = fmaxf(m, NEGF);
                float r = __expf(a1 - m) + __expf(a2 - m) + __expf(a3 - m);
                nxt[2 + s] = m + __logf(r) + lpv;
            }
            __syncthreads();
            float* tmp = cur; cur = nxt; nxt = tmp;
        }
    }

    if (s == 0) {
        int i1 = 2 * yl;
        int i2 = i1 - 1; if (i2 < 0) i2 = 0;
        float a = cur[2 + i1], cc = cur[2 + i2];
        float m = fmaxf(a, cc);
        float ll = m + __logf(__expf(a - m) + __expf(cc - m));
        float L = -ll;
        if (!isfinite(L) || L >= 1e29f) L = 0.0f;  // zero_infinity
        g_loss[b] = L;
    }
}

// ---------------- finalize: sum(loss) / sum(ys_lens) ----------------
__global__ void k_finalize(const int* __restrict__ ys_lens, float* __restrict__ out) {
    int t = threadIdx.x;
    float s  = (t < Bq) ? g_loss[t] : 0.0f;
    float yn = (t < Bq) ? (float)ys_lens[t] : 0.0f;
    #pragma unroll
    for (int o = 16; o > 0; o >>= 1) {
        s  += __shfl_xor_sync(0xffffffffu, s,  o);
        yn += __shfl_xor_sync(0xffffffffu, yn, o);
    }
    if (t == 0) out[0] = s / yn;
}

// ---------------- launch ----------------
extern "C" void kernel_launch(void* const* d_in, const int* in_sizes, int n_in,
                              void* d_out, int out_size) {
    (void)in_sizes; (void)n_in; (void)out_size;
    const float* hs      = (const float*)d_in[0];
    const int*   hlens   = (const int*)  d_in[1];
    const int*   ys_pad  = (const int*)  d_in[2];
    const int*   ys_lens = (const int*)  d_in[3];
    const float* W       = (const float*)d_in[4];
    const float* bias    = (const float*)d_in[5];
    float*       out     = (float*)d_out;

    cudaFuncSetAttribute(k_gemm, cudaFuncAttributeMaxDynamicSharedMemorySize, SM_TOTAL);
    cudaFuncSetAttribute(k_ctc,  cudaFuncAttributeMaxDynamicSharedMemorySize, 2*CHKB);

    k_cvt_hs<<<(BT*Dq/4 + 255)/256, 256>>>((const float4*)hs);
    k_cvt_wt<<<dim3(VP/32, Dq/32), dim3(32, 8)>>>(W);
    k_prep  <<<Bq, 256>>>(ys_pad);
    k_gemm  <<<dim3(NT, BT/128), 256, SM_TOTAL>>>(bias);
    k_lsedup<<<BT, 192>>>();
    k_ctc   <<<Bq, 288, 2*CHKB>>>(ys_pad, hlens, ys_lens);
    k_finalize<<<1, 32>>>(ys_lens, out);
}

// round 13
// speedup vs baseline: 1.5549x; 1.0923x over previous
#include <cuda_runtime.h>
#include <cuda_bf16.h>
#include <cstdint>
#include <math.h>

// Problem constants
#define Bq   16
#define Tq   1024
#define Dq   512
#define Vq   5000
#define Lq   128
#define VP   5120            // V padded to multiple of 128
#define NT   40              // VP / 128 column tiles
#define BT   (Bq*Tq)         // 16384 rows
#define LPS  132             // g_gbuf row stride (132*4 = 528 = 33*16 bytes)
#define NEGF (-1e30f)

// ---------------- scratch (static device globals; no allocation) ----------------
__device__ __align__(16) __nv_bfloat16 g_hsb[BT*Dq];      // hs in bf16
__device__ __align__(16) __nv_bfloat16 g_wt[VP*Dq];       // W transposed: [v][d], bf16, pad rows zero
__device__ __align__(16) float g_gbuf[BT*LPS];            // logits at first-occurrence symbols
__device__ __align__(16) float g_partial[BT*NT];          // per-(row, ntile) exp-sums
__device__ int   g_inv[Bq*Vq];                            // vocab -> first symbol index j (or -1)
__device__ int   g_rep[Bq*129];                           // j -> first occurrence j'
__device__ float g_loss[Bq];

// ---------------- helpers ----------------
__device__ __forceinline__ void cp16s(uint32_t smem_addr, const void* gmem) {
    asm volatile("cp.async.cg.shared.global [%0], [%1], 16;\n" :: "r"(smem_addr), "l"(gmem));
}
__device__ __forceinline__ void ldsm4(uint32_t& r0, uint32_t& r1, uint32_t& r2, uint32_t& r3,
                                      uint32_t addr) {
    asm volatile("ldmatrix.sync.aligned.m8n8.x4.shared.b16 {%0,%1,%2,%3}, [%4];\n"
                 : "=r"(r0), "=r"(r1), "=r"(r2), "=r"(r3) : "r"(addr));
}
__device__ __forceinline__ void mma_bf16(
    float& d0, float& d1, float& d2, float& d3,
    unsigned a0, unsigned a1, unsigned a2, unsigned a3,
    unsigned b0, unsigned b1)
{
    asm volatile(
        "mma.sync.aligned.m16n8k16.row.col.f32.bf16.bf16.f32 "
        "{%0,%1,%2,%3}, {%4,%5,%6,%7}, {%8,%9}, {%0,%1,%2,%3};\n"
        : "+f"(d0), "+f"(d1), "+f"(d2), "+f"(d3)
        : "r"(a0), "r"(a1), "r"(a2), "r"(a3), "r"(b0), "r"(b1));
}

// ---------------- conversion kernels ----------------
__global__ void k_cvt_hs(const float4* __restrict__ hs4) {
    int i = blockIdx.x * 256 + threadIdx.x;
    if (i < BT*Dq/4) {
        float4 v = hs4[i];
        __nv_bfloat162* o = (__nv_bfloat162*)g_hsb;
        o[2*i]   = __floats2bfloat162_rn(v.x, v.y);
        o[2*i+1] = __floats2bfloat162_rn(v.z, v.w);
    }
}

// Tiled transpose: W[D][V] f32 -> g_wt[VP][D] bf16 (pad rows v>=Vq zeroed)
__global__ void k_cvt_wt(const float* __restrict__ W) {
    __shared__ float tile[32][33];
    int v0 = blockIdx.x * 32, d0 = blockIdx.y * 32;
    int tx = threadIdx.x, ty = threadIdx.y;          // 32 x 8
    #pragma unroll
    for (int i = 0; i < 32; i += 8) {
        int d = d0 + ty + i, v = v0 + tx;
        tile[ty + i][tx] = (v < Vq) ? W[(size_t)d*Vq + v] : 0.0f;
    }
    __syncthreads();
    #pragma unroll
    for (int i = 0; i < 32; i += 8) {
        int v = v0 + ty + i, d = d0 + tx;
        g_wt[(size_t)v*Dq + d] = __float2bfloat16(tile[tx][ty + i]);
    }
}

// ---------------- per-batch symbol maps (parallel first-occurrence) ----------------
__global__ void k_prep(const int* __restrict__ ys_pad) {
    int b = blockIdx.x, tid = threadIdx.x;
    __shared__ int sym[129];
    if (tid == 0) sym[0] = 0;                              // blank
    if (tid >= 1 && tid <= 128) sym[tid] = ys_pad[b*Lq + tid - 1];
    for (int i = tid; i < Vq; i += 256) g_inv[b*Vq + i] = 0x7fffffff;
    __syncthreads();
    if (tid <= 128) atomicMin(&g_inv[b*Vq + sym[tid]], tid);
    __syncthreads();
    if (tid <= 128) g_rep[b*129 + tid] = g_inv[b*Vq + sym[tid]];
    __syncthreads();
    for (int i = tid; i < Vq; i += 256)
        if (g_inv[b*Vq + i] == 0x7fffffff) g_inv[b*Vq + i] = -1;
}

// ---------------- fused bf16 GEMM: 4-stage cp.async + ldmatrix + mma.sync ----------------
#define SMA_OFF   0
#define SMB_OFF   40960
#define SMBIAS    81920
#define SMINVS    82432
#define SMRSUM    82944
#define SM_TOTAL  83968
#define STAGE_B   10240

__global__ __launch_bounds__(256, 2) void k_gemm(const float* __restrict__ bias) {
    extern __shared__ __align__(16) char smem[];
    const int tid  = threadIdx.x;
    const int lane = tid & 31, wid = tid >> 5;
    const int g  = lane >> 2, tg = lane & 3;
    const int wm = wid & 3,  wn = wid >> 2;         // 4x2 warp grid, warp tile 32x64
    const int n0 = blockIdx.x * 128;
    const int rowg0 = blockIdx.y * 128;
    const int b = rowg0 >> 10;

    __nv_bfloat16* As = (__nv_bfloat16*)(smem + SMA_OFF);  // [stage][128][40]
    __nv_bfloat16* Bs = (__nv_bfloat16*)(smem + SMB_OFF);
    float* biass = (float*)(smem + SMBIAS);
    int*   invs  = (int*)  (smem + SMINVS);
    float* rsum  = (float*)(smem + SMRSUM);

    if (tid < 128) {
        int v = n0 + tid;
        invs[tid]  = (v < Vq) ? g_inv[b*Vq + v] : -1;
        biass[tid] = (v < Vq) ? bias[v] : 0.0f;
    }

    const int lr = lane & 15, lc = (lane >> 4) << 3;
    const uint32_t aBase = (uint32_t)__cvta_generic_to_shared(As);
    const uint32_t bBase = (uint32_t)__cvta_generic_to_shared(Bs);
    const uint32_t aoff0 = ((wm*32      + lr)*40 + lc)*2;
    const uint32_t aoff1 = ((wm*32 + 16 + lr)*40 + lc)*2;
    uint32_t boff[4];
    #pragma unroll
    for (int nt = 0; nt < 4; nt++) boff[nt] = ((wn*64 + nt*16 + lr)*40 + lc)*2;

    float acc[2][8][4];
    #pragma unroll
    for (int im = 0; im < 2; im++)
        #pragma unroll
        for (int in_ = 0; in_ < 8; in_++)
            #pragma unroll
            for (int c = 0; c < 4; c++) acc[im][in_][c] = 0.0f;

    const int lrow = tid >> 2, lkp = (tid & 3) << 3;
    const __nv_bfloat16* pA0 = g_hsb + (size_t)(rowg0 + lrow)*Dq + lkp;
    const __nv_bfloat16* pA1 = pA0 + (size_t)64*Dq;
    const __nv_bfloat16* pB0 = g_wt  + (size_t)(n0   + lrow)*Dq + lkp;
    const __nv_bfloat16* pB1 = pB0 + (size_t)64*Dq;
    const uint32_t dOff = (uint32_t)(lrow*40 + lkp)*2;
    const uint32_t dA = aBase + dOff, dB = bBase + dOff;

    auto loadStage = [&](int kt) {
        if (kt < 16) {
            const int st = kt & 3;
            const int ko = kt * 32;
            const uint32_t sOff = (uint32_t)st * STAGE_B;
            cp16s(dA + sOff,        pA0 + ko);
            cp16s(dA + sOff + 5120, pA1 + ko);
            cp16s(dB + sOff,        pB0 + ko);
            cp16s(dB + sOff + 5120, pB1 + ko);
        }
        asm volatile("cp.async.commit_group;\n");
    };

    loadStage(0);
    loadStage(1);
    loadStage(2);

    #pragma unroll 4
    for (int kt = 0; kt < 16; kt++) {
        asm volatile("cp.async.wait_group 2;\n");
        __syncthreads();
        loadStage(kt + 3);

        const uint32_t ab = aBase + (kt & 3)*STAGE_B;
        const uint32_t bb = bBase + (kt & 3)*STAGE_B;
        #pragma unroll
        for (int ks = 0; ks < 2; ks++) {
            uint32_t ko = ks * 32;
            uint32_t a0[4], a1[4], bm[4][4];
            ldsm4(a0[0], a0[1], a0[2], a0[3], ab + aoff0 + ko);
            ldsm4(a1[0], a1[1], a1[2], a1[3], ab + aoff1 + ko);
            #pragma unroll
            for (int nt = 0; nt < 4; nt++)
                ldsm4(bm[nt][0], bm[nt][1], bm[nt][2], bm[nt][3], bb + boff[nt] + ko);
            #pragma unroll
            for (int nt = 0; nt < 4; nt++) {
                #pragma unroll
                for (int h = 0; h < 2; h++) {
                    int in_ = nt*2 + h;
                    unsigned b0 = bm[nt][h], b1 = bm[nt][2 + h];
                    mma_bf16(acc[0][in_][0], acc[0][in_][1], acc[0][in_][2], acc[0][in_][3],
                             a0[0], a0[1], a0[2], a0[3], b0, b1);
                    mma_bf16(acc[1][in_][0], acc[1][in_][1], acc[1][in_][2], acc[1][in_][3],
                             a1[0], a1[1], a1[2], a1[3], b0, b1);
                }
            }
        }
    }
    __syncthreads();

    // Epilogue: bias add, exp-sum per row, sparse symbol scatter (gbuf stride = LPS)
    #pragma unroll
    for (int im = 0; im < 2; im++) {
        #pragma unroll
        for (int rh = 0; rh < 2; rh++) {
            int m = wm*32 + im*16 + g + rh*8;
            float* gb = g_gbuf + (size_t)(rowg0 + m)*LPS;
            float s = 0.0f;
            #pragma unroll
            for (int in_ = 0; in_ < 8; in_++) {
                #pragma unroll
                for (int cc = 0; cc < 2; cc++) {
                    int n = wn*64 + in_*8 + tg*2 + cc;
                    float x = acc[im][in_][rh*2 + cc] + biass[n];
                    if (n0 + n < Vq) {
                        s += __expf(x);
                        int j = invs[n];
                        if (j >= 0) gb[j] = x;
                    }
                }
            }
            s += __shfl_xor_sync(0xffffffffu, s, 1);
            s += __shfl_xor_sync(0xffffffffu, s, 2);
            if (tg == 0) rsum[m*2 + wn] = s;
        }
    }
    __syncthreads();
    if (tid < 128)
        g_partial[(size_t)(rowg0 + tid)*NT + blockIdx.x] = rsum[tid*2] + rsum[tid*2 + 1];
}

// ---------------- CTC forward: log-domain, fused lse + dup-replication, smem chunks ----------------
// Per 64-timestep chunk, stages raw logits (64 x 132 f32) AND partial exp-sums
// (64 x 40 f32) via double-buffered cp.async; computes lse per row in smem;
// inner loop reads lp = sg[row*132 + jrep] - slse[row] (jrep resolved per-thread once).
#define CHK    64
#define CHKB2  44032          // 64*132*4 + 64*40*4
#define SGF    (CHKB2/4)      // floats per buffer
__global__ __launch_bounds__(288) void k_ctc(const int* __restrict__ ys_pad,
                                             const int* __restrict__ hlens,
                                             const int* __restrict__ ys_lens) {
    extern __shared__ __align__(16) float sbuf[];  // 2 x (64x132 + 64x40) floats
    __shared__ float bufA[259], bufB[259];         // alpha at offset +2 (pads [0..1] = NEG)
    __shared__ float slse[2][64];
    __shared__ int ysS[128];

    const int b = blockIdx.x, s = threadIdx.x;     // 288 threads, states 0..256 active
    const int hl = hlens[b];
    const int yl = ys_lens[b];
    const float* gbB = g_gbuf    + (size_t)b * Tq * LPS;
    const float* ptB = g_partial + (size_t)b * Tq * NT;
    const uint32_t sBase = (uint32_t)__cvta_generic_to_shared(sbuf);

    if (s < 128) ysS[s] = ys_pad[b*Lq + s];
    if (s < 259) { bufA[s] = NEGF; bufB[s] = NEGF; }

    auto stage = [&](int c) {
        const float* srcG = gbB + ((size_t)(c << 6)) * LPS;
        const float* srcP = ptB + ((size_t)(c << 6)) * NT;
        uint32_t dG = sBase + (uint32_t)(c & 1) * CHKB2;
        uint32_t dP = dG + 33792;
        #pragma unroll
        for (int it = 0; it < 10; it++) {
            int i = s + it*288;                    // 2112 gbuf units + 640 partial units
            if (i < 2112) cp16s(dG + i*16, srcG + i*4);
            else if (i < 2752) { int k = i - 2112; cp16s(dP + k*16, srcP + k*4); }
        }
        asm volatile("cp.async.commit_group;\n");
    };
    stage(0);

    __syncthreads();                               // ysS ready
    const bool active = (s < 257);
    int jrep = 0;
    bool allow = false;
    if (active) {
        int jj = 0;
        if (s & 1) {
            int k = s >> 1;                        // s = 2k+1 -> label k, lp index k+1
            jj = k + 1;
            allow = (k == 0) || (ysS[k] != ysS[k - 1]);
        }
        jrep = g_rep[b*129 + jj];                  // first-occurrence index, fixed per thread
    }

    float* cur = bufA;
    float* nxt = bufB;
    const int nch = (hl + CHK - 1) >> 6;

    #pragma unroll 1
    for (int c = 0; c < nch; c++) {
        asm volatile("cp.async.wait_group 0;\n");  // chunk c staged
        __syncthreads();
        if (c + 1 < nch) stage(c + 1);             // overlap next chunk load with compute

        const float* sg = sbuf + (c & 1) * SGF;    // 64 x 132 logits
        const float* sp = sg + CHK*LPS;            // 64 x 40 partials
        if (s < 64) {
            float a = 0.0f;
            #pragma unroll
            for (int i = 0; i < NT; i++) a += sp[s*NT + i];
            slse[c & 1][s] = __logf(a);
        }
        __syncthreads();

        int t0;
        if (c == 0) {
            if (s < 2) cur[2 + s] = sg[jrep] - slse[0][0];   // alpha0 init (t=0 row)
            __syncthreads();
            t0 = 1;
        } else t0 = c << 6;
        const int t1 = min(hl, (c + 1) << 6);
        const int tb = c << 6;
        #pragma unroll 1
        for (int t = t0; t < t1; t++) {
            if (active) {
                int row = t - tb;
                float lpv = sg[row*LPS + jrep] - slse[c & 1][row];
                float a1 = cur[2 + s];
                float a2 = cur[1 + s];
                float a3 = allow ? cur[s] : NEGF;
                float m = fmaxf(fmaxf(a1, a2), a3);
                m = fmaxf(m, NEGF);
                float r = __expf(a1 - m) + __expf(a2 - m) + __expf(a3 - m);
                nxt[2 + s] = m + __logf(r) + lpv;
            }
            __syncthreads();
            float* tmp = cur; cur = nxt; nxt = tmp;
        }
    }

    if (s == 0) {
        int i1 = 2 * yl;
        int i2 = i1 - 1; if (i2 < 0) i2 = 0;
        float a = cur[2 + i1], cc = cur[2 + i2];
        float m = fmaxf(a, cc);
        float ll = m + __logf(__expf(a - m) + __expf(cc - m));
        float L = -ll;
        if (!isfinite(L) || L >= 1e29f) L = 0.0f;  // zero_infinity
        g_loss[b] = L;
    }
}

// ---------------- finalize: sum(loss) / sum(ys_lens) ----------------
__global__ void k_finalize(const int* __restrict__ ys_lens, float* __restrict__ out) {
    int t = threadIdx.x;
    float s  = (t < Bq) ? g_loss[t] : 0.0f;
    float yn = (t < Bq) ? (float)ys_lens[t] : 0.0f;
    #pragma unroll
    for (int o = 16; o > 0; o >>= 1) {
        s  += __shfl_xor_sync(0xffffffffu, s,  o);
        yn += __shfl_xor_sync(0xffffffffu, yn, o);
    }
    if (t == 0) out[0] = s / yn;
}

// ---------------- launch ----------------
extern "C" void kernel_launch(void* const* d_in, const int* in_sizes, int n_in,
                              void* d_out, int out_size) {
    (void)in_sizes; (void)n_in; (void)out_size;
    const float* hs      = (const float*)d_in[0];
    const int*   hlens   = (const int*)  d_in[1];
    const int*   ys_pad  = (const int*)  d_in[2];
    const int*   ys_lens = (const int*)  d_in[3];
    const float* W       = (const float*)d_in[4];
    const float* bias    = (const float*)d_in[5];
    float*       out     = (float*)d_out;

    cudaFuncSetAttribute(k_gemm, cudaFuncAttributeMaxDynamicSharedMemorySize, SM_TOTAL);
    cudaFuncSetAttribute(k_ctc,  cudaFuncAttributeMaxDynamicSharedMemorySize, 2*CHKB2);

    k_cvt_hs<<<(BT*Dq/4 + 255)/256, 256>>>((const float4*)hs);
    k_cvt_wt<<<dim3(VP/32, Dq/32), dim3(32, 8)>>>(W);
    k_prep  <<<Bq, 256>>>(ys_pad);
    k_gemm  <<<dim3(NT, BT/128), 256, SM_TOTAL>>>(bias);
    k_ctc   <<<Bq, 288, 2*CHKB2>>>(ys_pad, hlens, ys_lens);
    k_finalize<<<1, 32>>>(ys_lens, out);
}